// round 8
// baseline (speedup 1.0000x reference)
#include <cuda_runtime.h>
#include <math.h>
#include <stdint.h>

constexpr int B_    = 512;
constexpr int LEN_  = 1000;
constexpr int D_    = 16;
constexpr int HID_  = 256;
constexpr int WIN_  = 64;
constexpr int PAIRS_  = 120;
constexpr int LOGSIG_ = 136;
constexpr int K1_   = HID_ + LOGSIG_;   // 392
constexpr int K1P_  = 416;              // 13*32
constexpr int BT_   = 16;               // rows per CTA (parallel phase)
constexpr int BTS_  = 8;                // rows per CTA (serial phase)
constexpr int NCH_  = 32;               // cumsum time chunks
constexpr int WTS_  = 256 * 32;         // swizzled W tile (floats), parallel
constexpr int WROW_ = 36;               // padded W row (floats), serial
constexpr int WTP_  = 256 * WROW_;      // padded W tile (floats), serial

__device__ float g_X[(size_t)B_ * LEN_ * D_];
__device__ float g_ls[(size_t)WIN_ * B_ * LOGSIG_];
__device__ float g_lastall[24][(size_t)B_ * HID_];
__device__ float g_part[(size_t)B_ * NCH_ * D_];
__device__ float g_dts[LEN_ - 1];
__device__ int   g_tidx[WIN_ - 1];
__device__ int   g_sidx[WIN_ - 1];
__device__ int   g_seg[WIN_];
__device__ int   g_iu[PAIRS_];
__device__ int   g_ju[PAIRS_];

__host__ __device__ __forceinline__ double tb_d(int i) {
    return (i == LEN_ - 1) ? 1.0 : (double)i * (1.0 / 999.0);
}
__host__ __device__ __forceinline__ double tt_d(int k) {
    return (k == WIN_ - 1) ? 1.0 : (double)k * (1.0 / 63.0);
}

// Compute the reference's upd[64] schedule (exact double math). Host+device.
__host__ __device__ inline void compute_upd(bool upd[WIN_]) {
    double tu[20];
    for (int j = 0; j < 20; j++) tu[j] = tb_d(50 * j);
    int u_idx[63];
    for (int k = 1; k < 64; k++) {
        double t = tt_d(k);
        int uj = 0;
        for (int j = 0; j < 20; j++) if (tu[j] <= t) uj = j;
        u_idx[k - 1] = uj;
    }
    double qt[64]; int qn = 0, last = -1;
    for (int k = 0; k < 63; k++) {
        int iu = u_idx[k] < 0 ? 0 : u_idx[k];
        if (iu != last) { qt[qn++] = tu[iu]; last = iu; }
    }
    qt[qn++] = tt_d(63);
    int qh = 0;
    for (int i = 0; i < 64; i++) {
        upd[i] = false;
        if (qh < qn && tt_d(i) >= qt[qh]) { qh++; upd[i] = true; }
    }
}

__global__ void sched_kernel() {
    int tid = threadIdx.x;
    for (int i = tid; i < LEN_ - 1; i += blockDim.x)
        g_dts[i] = sqrtf((float)(tb_d(i + 1) - tb_d(i)));
    if (tid < WIN_ - 1) {
        double t = tt_d(tid + 1);
        int ti = 0;
        for (int i = 0; i < LEN_; i++) if (tb_d(i) <= t) ti = i;
        g_tidx[tid] = ti;
        int uj = 0;
        for (int j = 0; j < LEN_ / 50; j++) if (tb_d(50 * j) <= t) uj = j;
        g_sidx[tid] = 50 * uj;
    }
    if (tid >= 64 && tid < 64 + PAIRS_) {
        int p = tid - 64;
        int i = 0, accp = 0;
        while (accp + (D_ - 1 - i) <= p) { accp += D_ - 1 - i; i++; }
        g_iu[p] = i;
        g_ju[p] = i + 1 + (p - accp);
    }
    if (tid == 0) {
        bool upd[WIN_];
        compute_upd(upd);
        int s = 0;
        for (int i = 0; i < WIN_; i++) { g_seg[i] = s; if (upd[i]) s++; }
    }
}

__global__ void zero_last_kernel() {
    int g = blockIdx.x * blockDim.x + threadIdx.x;
    if (g < B_ * HID_) g_lastall[0][g] = 0.f;
}

__device__ __forceinline__ void chunk_rng(int c, int& t0, int& t1) {
    t0 = (c * 999) / NCH_ + 1;
    t1 = ((c + 1) * 999) / NCH_;
}

__global__ void cumsum_part_kernel(const float* __restrict__ z) {
    int g = blockIdx.x * blockDim.x + threadIdx.x;
    int d4 = g & 3, c = (g >> 2) & (NCH_ - 1), b = g >> 7;
    int t0, t1; chunk_rng(c, t0, t1);
    const float4* zp = reinterpret_cast<const float4*>(z + (size_t)b * LEN_ * D_) + d4;
    float4 s = make_float4(0.f, 0.f, 0.f, 0.f);
    for (int t = t0; t <= t1; t++) {
        float dt = g_dts[t - 1];
        float4 zv = zp[t * 4];
        s.x += zv.x * dt; s.y += zv.y * dt; s.z += zv.z * dt; s.w += zv.w * dt;
    }
    reinterpret_cast<float4*>(g_part + ((size_t)b * NCH_ + c) * D_)[d4] = s;
}

__global__ void cumsum_write_kernel(const float* __restrict__ z) {
    int g = blockIdx.x * blockDim.x + threadIdx.x;
    int d4 = g & 3, c = (g >> 2) & (NCH_ - 1), b = g >> 7;
    float4 acc = make_float4(0.f, 0.f, 0.f, 0.f);
    for (int cc = 0; cc < c; cc++) {
        float4 p = reinterpret_cast<const float4*>(g_part + ((size_t)b * NCH_ + cc) * D_)[d4];
        acc.x += p.x; acc.y += p.y; acc.z += p.z; acc.w += p.w;
    }
    int t0, t1; chunk_rng(c, t0, t1);
    const float4* zp = reinterpret_cast<const float4*>(z + (size_t)b * LEN_ * D_) + d4;
    float4* xp = reinterpret_cast<float4*>(g_X + (size_t)b * LEN_ * D_) + d4;
    if (c == 0) xp[0] = make_float4(0.f, 0.f, 0.f, 0.f);
    for (int t = t0; t <= t1; t++) {
        float dt = g_dts[t - 1];
        float4 zv = zp[t * 4];
        acc.x += zv.x * dt; acc.y += zv.y * dt; acc.z += zv.z * dt; acc.w += zv.w * dt;
        xp[t * 4] = acc;
    }
}

__global__ void logsig_kernel() {
    int kk = blockIdx.x, b = blockIdx.y, tid = threadIdx.x;
    if (kk == 0) {
        if (tid < LOGSIG_) g_ls[(size_t)b * LOGSIG_ + tid] = 0.f;
        return;
    }
    int k = kk - 1, t1 = g_tidx[k], s0 = g_sidx[k];
    int nrow = t1 - s0 + 1;                          // <= 50
    __shared__ float sX[50 * 16];
    const float* xb = g_X + ((size_t)b * LEN_ + s0) * D_;
    for (int e = tid; e < (nrow * D_) >> 2; e += blockDim.x)
        reinterpret_cast<float4*>(sX)[e] = reinterpret_cast<const float4*>(xb)[e];
    __syncthreads();
    float* outp = g_ls + ((size_t)kk * B_ + b) * LOGSIG_;
    if (tid < D_) {
        outp[tid] = sX[(t1 - s0) * D_ + tid];
    } else if (tid < LOGSIG_) {
        int p = tid - D_, iu = g_iu[p], ju = g_ju[p];
        float xi = sX[iu], xj = sX[ju];
        float acc = 0.f;
        for (int s = 1; s < nrow; s++) {
            float yi = sX[s * D_ + iu], yj = sX[s * D_ + ju];
            acc += xi * (yj - xj) - xj * (yi - xi);
            xi = yi; xj = yj;
        }
        outp[tid] = 0.5f * acc;
    }
}

__device__ __forceinline__ void ffma2(unsigned long long& acc,
                                      unsigned long long a, unsigned long long b) {
    asm("fma.rn.f32x2 %0, %1, %2, %0;" : "+l"(acc) : "l"(a), "l"(b));
}

// ============ PARALLEL PHASE (v6 machinery: swizzled W tiles + shfl x) ============

__device__ __forceinline__ void stage_sw256(const float* __restrict__ Wg, int Ktrue,
                                            int k0, float* sWbuf, int tid) {
    #pragma unroll
    for (int u = 0; u < 8; u++) {
        int g = (u << 8) + tid;
        int row = g >> 3;
        int c4  = g & 7;
        int k   = k0 + (c4 << 2);
        uint32_t dst = (uint32_t)__cvta_generic_to_shared(
            sWbuf + row * 32 + ((c4 ^ (row & 7)) << 2));
        bool valid = (k + 4 <= Ktrue);
        const float* src = valid ? (Wg + (size_t)row * Ktrue + k) : Wg;
        int sz = valid ? 16 : 0;
        asm volatile("cp.async.cg.shared.global [%0], [%1], 16, %2;"
                     :: "r"(dst), "l"(src), "r"(sz));
    }
    asm volatile("cp.async.commit_group;");
}

__device__ __forceinline__ void gemm44(
    const float* __restrict__ Wg, int Ktrue, int nch,
    const float* __restrict__ sin, int sstride,
    float* __restrict__ sW, int tid, float outv[4][4])
{
    const int jt = tid & 63;
    const int rg = tid >> 6;
    const int lane = tid & 31;

    unsigned long long acc[4][4];
    #pragma unroll
    for (int q = 0; q < 4; q++)
        #pragma unroll
        for (int r = 0; r < 4; r++) acc[q][r] = 0ULL;

    stage_sw256(Wg, Ktrue, 0, sW, tid);
    for (int ch = 0; ch < nch; ch++) {
        if (ch + 1 < nch) {
            stage_sw256(Wg, Ktrue, (ch + 1) << 5, sW + ((ch + 1) & 1) * WTS_, tid);
            asm volatile("cp.async.wait_group 1;");
        } else {
            asm volatile("cp.async.wait_group 0;");
        }
        __syncthreads();
        const float* cur = sW + (ch & 1) * WTS_;
        const int k0 = ch << 5;

        ulonglong2 xs = *reinterpret_cast<const ulonglong2*>(
            sin + (rg * 4 + (lane >> 3)) * sstride + k0 + ((lane & 7) << 2));

        #pragma unroll
        for (int c4 = 0; c4 < 8; c4++) {
            ulonglong2 wv[4];
            #pragma unroll
            for (int q = 0; q < 4; q++) {
                int row = jt + (q << 6);
                wv[q] = *reinterpret_cast<const ulonglong2*>(
                    cur + row * 32 + ((c4 ^ (row & 7)) << 2));
            }
            #pragma unroll
            for (int rr = 0; rr < 4; rr++) {
                const int src = (rr << 3) + c4;
                unsigned long long xa = __shfl_sync(0xffffffffu, xs.x, src);
                unsigned long long xb = __shfl_sync(0xffffffffu, xs.y, src);
                #pragma unroll
                for (int q = 0; q < 4; q++) {
                    ffma2(acc[q][rr], wv[q].x, xa);
                    ffma2(acc[q][rr], wv[q].y, xb);
                }
            }
        }
        __syncthreads();
    }
    #pragma unroll
    for (int q = 0; q < 4; q++)
        #pragma unroll
        for (int r = 0; r < 4; r++) {
            float lo = __uint_as_float((unsigned)acc[q][r]);
            float hi = __uint_as_float((unsigned)(acc[q][r] >> 32));
            outv[q][r] = lo + hi;
        }
}

// All 64 steps in one launch: 32 CTAs per step, reads state via g_seg.
__global__ void __launch_bounds__(256, 2)
rnn_all_kernel(const float* __restrict__ W1, const float* __restrict__ b1,
               const float* __restrict__ W2, const float* __restrict__ b2,
               const float* __restrict__ W3, const float* __restrict__ b3,
               const float* __restrict__ Wl, float* __restrict__ out)
{
    extern __shared__ float smem[];
    float* sW = smem;                       // 2 * 256*32 swizzled
    float* R0 = sW + 2 * WTS_;              // 16*416
    float* R1 = R0 + BT_ * K1P_;            // 16*256

    const int tid  = threadIdx.x;
    const int jt   = tid & 63;
    const int rg   = tid >> 6;
    const int step = blockIdx.x >> 5;       // 32 CTAs per step
    const int b0   = (blockIdx.x & 31) * BT_;
    const float* last_in = g_lastall[g_seg[step]];

    for (int r = 0; r < BT_; r++) {
        int b = b0 + r;
        for (int c = tid; c < K1P_; c += 256) {
            float v = 0.f;
            if (c < HID_)     v = last_in[(size_t)b * HID_ + c];
            else if (c < K1_) v = g_ls[((size_t)step * B_ + b) * LOGSIG_ + (c - HID_)];
            R0[r * K1P_ + c] = v;
        }
    }

    float v[4][4];

    gemm44(W1, K1_, K1P_ / 32, R0, K1P_, sW, tid, v);
    #pragma unroll
    for (int q = 0; q < 4; q++) {
        int j = jt + (q << 6); float bb = b1[j];
        #pragma unroll
        for (int rr = 0; rr < 4; rr++)
            R1[(rg * 4 + rr) * HID_ + j] = fmaxf(v[q][rr] + bb, 0.f);
    }
    __syncthreads();

    gemm44(W2, HID_, HID_ / 32, R1, HID_, sW, tid, v);
    __syncthreads();
    #pragma unroll
    for (int q = 0; q < 4; q++) {
        int j = jt + (q << 6); float bb = b2[j];
        #pragma unroll
        for (int rr = 0; rr < 4; rr++)
            R0[(rg * 4 + rr) * HID_ + j] = fmaxf(v[q][rr] + bb, 0.f);
    }
    __syncthreads();

    gemm44(W3, HID_, HID_ / 32, R0, HID_, sW, tid, v);
    __syncthreads();
    #pragma unroll
    for (int q = 0; q < 4; q++) {
        int j = jt + (q << 6); float bb = b3[j];
        #pragma unroll
        for (int rr = 0; rr < 4; rr++)
            R1[(rg * 4 + rr) * HID_ + j] = tanhf(v[q][rr] + bb);
    }
    __syncthreads();

    gemm44(Wl, HID_, HID_ / 32, R1, HID_, sW, tid, v);
    #pragma unroll
    for (int q = 0; q < 4; q++) {
        int j = jt + (q << 6);
        #pragma unroll
        for (int rr = 0; rr < 4; rr++) {
            int b = b0 + rg * 4 + rr;
            out[((size_t)b * WIN_ + step) * HID_ + j] = v[q][rr];
        }
    }
}

// ============ SERIAL PHASE: one update step, layers 1-3 only ============

__device__ __forceinline__ void stage_pad512(const float* __restrict__ Wg, int Ktrue,
                                             int k0, float* sWbuf, int tid) {
    #pragma unroll
    for (int u = 0; u < 4; u++) {
        int g = (u << 9) + tid;          // 2048 float4s
        int row = g >> 3;
        int c4  = g & 7;
        int k   = k0 + (c4 << 2);
        uint32_t dst = (uint32_t)__cvta_generic_to_shared(sWbuf + row * WROW_ + (c4 << 2));
        bool valid = (k + 4 <= Ktrue);
        const float* src = valid ? (Wg + (size_t)row * Ktrue + k) : Wg;
        int sz = valid ? 16 : 0;
        asm volatile("cp.async.cg.shared.global [%0], [%1], 16, %2;"
                     :: "r"(dst), "l"(src), "r"(sz));
    }
    asm volatile("cp.async.commit_group;");
}

// thread owns column j = tid&255, rows r0..r0+3 (r0 = (tid>>8)*4)
__device__ __forceinline__ void gemm4s(
    const float* __restrict__ Wg, int Ktrue, int nch,
    const float* __restrict__ sin, int sstride,
    float* __restrict__ sW, int tid, int j, int r0, float outv[4])
{
    unsigned long long acc[4];
    #pragma unroll
    for (int r = 0; r < 4; r++) acc[r] = 0ULL;

    stage_pad512(Wg, Ktrue, 0, sW, tid);
    for (int ch = 0; ch < nch; ch++) {
        if (ch + 1 < nch) {
            stage_pad512(Wg, Ktrue, (ch + 1) << 5, sW + ((ch + 1) & 1) * WTP_, tid);
            asm volatile("cp.async.wait_group 1;");
        } else {
            asm volatile("cp.async.wait_group 0;");
        }
        __syncthreads();
        const float* cur = sW + (ch & 1) * WTP_;
        const int k0 = ch << 5;

        ulonglong2 w2[8];
        #pragma unroll
        for (int q = 0; q < 8; q++)
            w2[q] = *reinterpret_cast<const ulonglong2*>(cur + j * WROW_ + (q << 2));

        #pragma unroll
        for (int r = 0; r < 4; r++) {
            const float* xr = sin + (r0 + r) * sstride + k0;
            #pragma unroll
            for (int q = 0; q < 8; q++) {
                ulonglong2 x2 = *reinterpret_cast<const ulonglong2*>(xr + (q << 2));
                ffma2(acc[r], w2[q].x, x2.x);
                ffma2(acc[r], w2[q].y, x2.y);
            }
        }
        __syncthreads();
    }
    #pragma unroll
    for (int r = 0; r < 4; r++) {
        float lo = __uint_as_float((unsigned)acc[r]);
        float hi = __uint_as_float((unsigned)(acc[r] >> 32));
        outv[r] = lo + hi;
    }
}

__global__ void __launch_bounds__(512, 1)
serial_step_kernel(const float* __restrict__ W1, const float* __restrict__ b1,
                   const float* __restrict__ W2, const float* __restrict__ b2,
                   const float* __restrict__ W3, const float* __restrict__ b3,
                   int sidx, int step)
{
    extern __shared__ float smem[];
    float* sW = smem;                       // 2 * 256*36
    float* R0 = sW + 2 * WTP_;              // 8*416
    float* R1 = R0 + BTS_ * K1P_;           // 8*256

    const float* last_in  = g_lastall[sidx];
    float*       last_out = g_lastall[sidx + 1];

    const int tid = threadIdx.x;
    const int j   = tid & 255;
    const int r0  = (tid >> 8) * 4;
    const int b0  = blockIdx.x * BTS_;

    for (int r = 0; r < BTS_; r++) {
        int b = b0 + r;
        for (int c = tid; c < K1P_; c += 512) {
            float v = 0.f;
            if (c < HID_)     v = last_in[(size_t)b * HID_ + c];
            else if (c < K1_) v = g_ls[((size_t)step * B_ + b) * LOGSIG_ + (c - HID_)];
            R0[r * K1P_ + c] = v;
        }
    }

    float v[4];

    gemm4s(W1, K1_, K1P_ / 32, R0, K1P_, sW, tid, j, r0, v);
    {
        float bb = b1[j];
        #pragma unroll
        for (int r = 0; r < 4; r++)
            R1[(r0 + r) * HID_ + j] = fmaxf(v[r] + bb, 0.f);
    }
    __syncthreads();

    gemm4s(W2, HID_, HID_ / 32, R1, HID_, sW, tid, j, r0, v);
    __syncthreads();
    {
        float bb = b2[j];
        #pragma unroll
        for (int r = 0; r < 4; r++)
            R0[(r0 + r) * HID_ + j] = fmaxf(v[r] + bb, 0.f);
    }
    __syncthreads();

    gemm4s(W3, HID_, HID_ / 32, R0, HID_, sW, tid, j, r0, v);
    {
        float bb = b3[j];
        #pragma unroll
        for (int r = 0; r < 4; r++)
            last_out[(size_t)(b0 + r0 + r) * HID_ + j] = tanhf(v[r] + bb);
    }
}

extern "C" void kernel_launch(void* const* d_in, const int* in_sizes, int n_in,
                              void* d_out, int out_size) {
    (void)in_sizes; (void)n_in; (void)out_size;
    const float* z  = (const float*)d_in[0];
    const float* W1 = (const float*)d_in[1];
    const float* b1 = (const float*)d_in[2];
    const float* W2 = (const float*)d_in[3];
    const float* b2 = (const float*)d_in[4];
    const float* W3 = (const float*)d_in[5];
    const float* b3 = (const float*)d_in[6];
    const float* Wl = (const float*)d_in[7];
    float* out = (float*)d_out;

    const size_t smem_par =
        (2 * WTS_ + BT_ * K1P_ + BT_ * HID_) * sizeof(float);     // ~108 KB
    const size_t smem_ser =
        (2 * WTP_ + BTS_ * K1P_ + BTS_ * HID_) * sizeof(float);   // ~95 KB
    cudaFuncSetAttribute(rnn_all_kernel,
                         cudaFuncAttributeMaxDynamicSharedMemorySize, (int)smem_par);
    cudaFuncSetAttribute(serial_step_kernel,
                         cudaFuncAttributeMaxDynamicSharedMemorySize, (int)smem_ser);

    sched_kernel<<<1, 256>>>();
    zero_last_kernel<<<(B_ * HID_ + 255) / 256, 256>>>();
    cumsum_part_kernel<<<(B_ * NCH_ * 4) / 256, 256>>>(z);
    cumsum_write_kernel<<<(B_ * NCH_ * 4) / 256, 256>>>(z);
    logsig_kernel<<<dim3(WIN_, B_), 160>>>();

    // host-side upd schedule -> update step list
    bool upd[WIN_];
    compute_upd(upd);

    int s = 0;
    for (int i = 0; i < WIN_; i++) {
        if (upd[i]) {
            serial_step_kernel<<<B_ / BTS_, 512, smem_ser>>>(
                W1, b1, W2, b2, W3, b3, s, i);
            s++;
        }
    }

    rnn_all_kernel<<<WIN_ * (B_ / BT_), 256, smem_par>>>(
        W1, b1, W2, b2, W3, b3, Wl, out);
}

// round 9
// speedup vs baseline: 1.0864x; 1.0864x over previous
#include <cuda_runtime.h>
#include <math.h>
#include <stdint.h>

constexpr int B_    = 512;
constexpr int LEN_  = 1000;
constexpr int D_    = 16;
constexpr int HID_  = 256;
constexpr int WIN_  = 64;
constexpr int PAIRS_  = 120;
constexpr int LOGSIG_ = 136;
constexpr int K1_   = HID_ + LOGSIG_;   // 392
constexpr int K1P_  = 416;              // 13*32
constexpr int BT_   = 16;               // rows per CTA (parallel phase)
constexpr int NCH_  = 32;               // cumsum time chunks
constexpr int WTS_  = 256 * 32;         // swizzled W tile (floats), parallel
constexpr int S_TILES_ = 13 + 8 + 8;    // serial W chunk-tiles (29)

__device__ float g_X[(size_t)B_ * LEN_ * D_];
__device__ float g_ls[(size_t)WIN_ * B_ * LOGSIG_];
__device__ float g_lastall[24][(size_t)B_ * HID_];
__device__ float g_h1[(size_t)B_ * HID_];
__device__ float g_h2[(size_t)B_ * HID_];
__device__ float g_part[(size_t)B_ * NCH_ * D_];
__device__ float g_dts[LEN_ - 1];
__device__ int   g_tidx[WIN_ - 1];
__device__ int   g_sidx[WIN_ - 1];
__device__ int   g_seg[WIN_];
__device__ int   g_ustep[WIN_];
__device__ int   g_nupd;
__device__ int   g_barcnt;
__device__ int   g_iu[PAIRS_];
__device__ int   g_ju[PAIRS_];

__host__ __device__ __forceinline__ double tb_d(int i) {
    return (i == LEN_ - 1) ? 1.0 : (double)i * (1.0 / 999.0);
}
__host__ __device__ __forceinline__ double tt_d(int k) {
    return (k == WIN_ - 1) ? 1.0 : (double)k * (1.0 / 63.0);
}

__host__ __device__ inline void compute_upd(bool upd[WIN_]) {
    double tu[20];
    for (int j = 0; j < 20; j++) tu[j] = tb_d(50 * j);
    int u_idx[63];
    for (int k = 1; k < 64; k++) {
        double t = tt_d(k);
        int uj = 0;
        for (int j = 0; j < 20; j++) if (tu[j] <= t) uj = j;
        u_idx[k - 1] = uj;
    }
    double qt[64]; int qn = 0, last = -1;
    for (int k = 0; k < 63; k++) {
        int iu = u_idx[k] < 0 ? 0 : u_idx[k];
        if (iu != last) { qt[qn++] = tu[iu]; last = iu; }
    }
    qt[qn++] = tt_d(63);
    int qh = 0;
    for (int i = 0; i < 64; i++) {
        upd[i] = false;
        if (qh < qn && tt_d(i) >= qt[qh]) { qh++; upd[i] = true; }
    }
}

__global__ void sched_kernel() {
    int tid = threadIdx.x;
    for (int i = tid; i < LEN_ - 1; i += blockDim.x)
        g_dts[i] = sqrtf((float)(tb_d(i + 1) - tb_d(i)));
    if (tid < WIN_ - 1) {
        double t = tt_d(tid + 1);
        int ti = 0;
        for (int i = 0; i < LEN_; i++) if (tb_d(i) <= t) ti = i;
        g_tidx[tid] = ti;
        int uj = 0;
        for (int j = 0; j < LEN_ / 50; j++) if (tb_d(50 * j) <= t) uj = j;
        g_sidx[tid] = 50 * uj;
    }
    if (tid >= 64 && tid < 64 + PAIRS_) {
        int p = tid - 64;
        int i = 0, accp = 0;
        while (accp + (D_ - 1 - i) <= p) { accp += D_ - 1 - i; i++; }
        g_iu[p] = i;
        g_ju[p] = i + 1 + (p - accp);
    }
    if (tid == 0) {
        bool upd[WIN_];
        compute_upd(upd);
        int s = 0;
        for (int i = 0; i < WIN_; i++) {
            g_seg[i] = s;
            if (upd[i]) { g_ustep[s] = i; s++; }
        }
        g_nupd = s;
    }
}

__global__ void zero_last_kernel() {
    int g = blockIdx.x * blockDim.x + threadIdx.x;
    if (g < B_ * HID_) g_lastall[0][g] = 0.f;
    if (g == 0) g_barcnt = 0;
}

__device__ __forceinline__ void chunk_rng(int c, int& t0, int& t1) {
    t0 = (c * 999) / NCH_ + 1;
    t1 = ((c + 1) * 999) / NCH_;
}

__global__ void cumsum_part_kernel(const float* __restrict__ z) {
    int g = blockIdx.x * blockDim.x + threadIdx.x;
    int d4 = g & 3, c = (g >> 2) & (NCH_ - 1), b = g >> 7;
    int t0, t1; chunk_rng(c, t0, t1);
    const float4* zp = reinterpret_cast<const float4*>(z + (size_t)b * LEN_ * D_) + d4;
    float4 s = make_float4(0.f, 0.f, 0.f, 0.f);
    for (int t = t0; t <= t1; t++) {
        float dt = g_dts[t - 1];
        float4 zv = zp[t * 4];
        s.x += zv.x * dt; s.y += zv.y * dt; s.z += zv.z * dt; s.w += zv.w * dt;
    }
    reinterpret_cast<float4*>(g_part + ((size_t)b * NCH_ + c) * D_)[d4] = s;
}

__global__ void cumsum_write_kernel(const float* __restrict__ z) {
    int g = blockIdx.x * blockDim.x + threadIdx.x;
    int d4 = g & 3, c = (g >> 2) & (NCH_ - 1), b = g >> 7;
    float4 acc = make_float4(0.f, 0.f, 0.f, 0.f);
    for (int cc = 0; cc < c; cc++) {
        float4 p = reinterpret_cast<const float4*>(g_part + ((size_t)b * NCH_ + cc) * D_)[d4];
        acc.x += p.x; acc.y += p.y; acc.z += p.z; acc.w += p.w;
    }
    int t0, t1; chunk_rng(c, t0, t1);
    const float4* zp = reinterpret_cast<const float4*>(z + (size_t)b * LEN_ * D_) + d4;
    float4* xp = reinterpret_cast<float4*>(g_X + (size_t)b * LEN_ * D_) + d4;
    if (c == 0) xp[0] = make_float4(0.f, 0.f, 0.f, 0.f);
    for (int t = t0; t <= t1; t++) {
        float dt = g_dts[t - 1];
        float4 zv = zp[t * 4];
        acc.x += zv.x * dt; acc.y += zv.y * dt; acc.z += zv.z * dt; acc.w += zv.w * dt;
        xp[t * 4] = acc;
    }
}

__global__ void logsig_kernel() {
    int kk = blockIdx.x, b = blockIdx.y, tid = threadIdx.x;
    if (kk == 0) {
        if (tid < LOGSIG_) g_ls[(size_t)b * LOGSIG_ + tid] = 0.f;
        return;
    }
    int k = kk - 1, t1 = g_tidx[k], s0 = g_sidx[k];
    int nrow = t1 - s0 + 1;                          // <= 50
    __shared__ float sX[50 * 16];
    const float* xb = g_X + ((size_t)b * LEN_ + s0) * D_;
    for (int e = tid; e < (nrow * D_) >> 2; e += blockDim.x)
        reinterpret_cast<float4*>(sX)[e] = reinterpret_cast<const float4*>(xb)[e];
    __syncthreads();
    float* outp = g_ls + ((size_t)kk * B_ + b) * LOGSIG_;
    if (tid < D_) {
        outp[tid] = sX[(t1 - s0) * D_ + tid];
    } else if (tid < LOGSIG_) {
        int p = tid - D_, iu = g_iu[p], ju = g_ju[p];
        float xi = sX[iu], xj = sX[ju];
        float acc = 0.f;
        for (int s = 1; s < nrow; s++) {
            float yi = sX[s * D_ + iu], yj = sX[s * D_ + ju];
            acc += xi * (yj - xj) - xj * (yi - xi);
            xi = yi; xj = yj;
        }
        outp[tid] = 0.5f * acc;
    }
}

__device__ __forceinline__ void ffma2(unsigned long long& acc,
                                      unsigned long long a, unsigned long long b) {
    asm("fma.rn.f32x2 %0, %1, %2, %0;" : "+l"(acc) : "l"(a), "l"(b));
}

// ============ PARALLEL PHASE (unchanged from R8: swizzled W tiles + shfl x) ============

__device__ __forceinline__ void stage_sw256(const float* __restrict__ Wg, int Ktrue,
                                            int k0, float* sWbuf, int tid) {
    #pragma unroll
    for (int u = 0; u < 8; u++) {
        int g = (u << 8) + tid;
        int row = g >> 3;
        int c4  = g & 7;
        int k   = k0 + (c4 << 2);
        uint32_t dst = (uint32_t)__cvta_generic_to_shared(
            sWbuf + row * 32 + ((c4 ^ (row & 7)) << 2));
        bool valid = (k + 4 <= Ktrue);
        const float* src = valid ? (Wg + (size_t)row * Ktrue + k) : Wg;
        int sz = valid ? 16 : 0;
        asm volatile("cp.async.cg.shared.global [%0], [%1], 16, %2;"
                     :: "r"(dst), "l"(src), "r"(sz));
    }
    asm volatile("cp.async.commit_group;");
}

__device__ __forceinline__ void gemm44(
    const float* __restrict__ Wg, int Ktrue, int nch,
    const float* __restrict__ sin, int sstride,
    float* __restrict__ sW, int tid, float outv[4][4])
{
    const int jt = tid & 63;
    const int rg = tid >> 6;
    const int lane = tid & 31;

    unsigned long long acc[4][4];
    #pragma unroll
    for (int q = 0; q < 4; q++)
        #pragma unroll
        for (int r = 0; r < 4; r++) acc[q][r] = 0ULL;

    stage_sw256(Wg, Ktrue, 0, sW, tid);
    for (int ch = 0; ch < nch; ch++) {
        if (ch + 1 < nch) {
            stage_sw256(Wg, Ktrue, (ch + 1) << 5, sW + ((ch + 1) & 1) * WTS_, tid);
            asm volatile("cp.async.wait_group 1;");
        } else {
            asm volatile("cp.async.wait_group 0;");
        }
        __syncthreads();
        const float* cur = sW + (ch & 1) * WTS_;
        const int k0 = ch << 5;

        ulonglong2 xs = *reinterpret_cast<const ulonglong2*>(
            sin + (rg * 4 + (lane >> 3)) * sstride + k0 + ((lane & 7) << 2));

        #pragma unroll
        for (int c4 = 0; c4 < 8; c4++) {
            ulonglong2 wv[4];
            #pragma unroll
            for (int q = 0; q < 4; q++) {
                int row = jt + (q << 6);
                wv[q] = *reinterpret_cast<const ulonglong2*>(
                    cur + row * 32 + ((c4 ^ (row & 7)) << 2));
            }
            #pragma unroll
            for (int rr = 0; rr < 4; rr++) {
                const int src = (rr << 3) + c4;
                unsigned long long xa = __shfl_sync(0xffffffffu, xs.x, src);
                unsigned long long xb = __shfl_sync(0xffffffffu, xs.y, src);
                #pragma unroll
                for (int q = 0; q < 4; q++) {
                    ffma2(acc[q][rr], wv[q].x, xa);
                    ffma2(acc[q][rr], wv[q].y, xb);
                }
            }
        }
        __syncthreads();
    }
    #pragma unroll
    for (int q = 0; q < 4; q++)
        #pragma unroll
        for (int r = 0; r < 4; r++) {
            float lo = __uint_as_float((unsigned)acc[q][r]);
            float hi = __uint_as_float((unsigned)(acc[q][r] >> 32));
            outv[q][r] = lo + hi;
        }
}

__global__ void __launch_bounds__(256, 2)
rnn_all_kernel(const float* __restrict__ W1, const float* __restrict__ b1,
               const float* __restrict__ W2, const float* __restrict__ b2,
               const float* __restrict__ W3, const float* __restrict__ b3,
               const float* __restrict__ Wl, float* __restrict__ out)
{
    extern __shared__ float smem[];
    float* sW = smem;                       // 2 * 256*32 swizzled
    float* R0 = sW + 2 * WTS_;              // 16*416
    float* R1 = R0 + BT_ * K1P_;            // 16*256

    const int tid  = threadIdx.x;
    const int jt   = tid & 63;
    const int rg   = tid >> 6;
    const int step = blockIdx.x >> 5;       // 32 CTAs per step
    const int b0   = (blockIdx.x & 31) * BT_;
    const float* last_in = g_lastall[g_seg[step]];

    for (int r = 0; r < BT_; r++) {
        int b = b0 + r;
        for (int c = tid; c < K1P_; c += 256) {
            float v = 0.f;
            if (c < HID_)     v = last_in[(size_t)b * HID_ + c];
            else if (c < K1_) v = g_ls[((size_t)step * B_ + b) * LOGSIG_ + (c - HID_)];
            R0[r * K1P_ + c] = v;
        }
    }

    float v[4][4];

    gemm44(W1, K1_, K1P_ / 32, R0, K1P_, sW, tid, v);
    #pragma unroll
    for (int q = 0; q < 4; q++) {
        int j = jt + (q << 6); float bb = b1[j];
        #pragma unroll
        for (int rr = 0; rr < 4; rr++)
            R1[(rg * 4 + rr) * HID_ + j] = fmaxf(v[q][rr] + bb, 0.f);
    }
    __syncthreads();

    gemm44(W2, HID_, HID_ / 32, R1, HID_, sW, tid, v);
    __syncthreads();
    #pragma unroll
    for (int q = 0; q < 4; q++) {
        int j = jt + (q << 6); float bb = b2[j];
        #pragma unroll
        for (int rr = 0; rr < 4; rr++)
            R0[(rg * 4 + rr) * HID_ + j] = fmaxf(v[q][rr] + bb, 0.f);
    }
    __syncthreads();

    gemm44(W3, HID_, HID_ / 32, R0, HID_, sW, tid, v);
    __syncthreads();
    #pragma unroll
    for (int q = 0; q < 4; q++) {
        int j = jt + (q << 6); float bb = b3[j];
        #pragma unroll
        for (int rr = 0; rr < 4; rr++)
            R1[(rg * 4 + rr) * HID_ + j] = tanhf(v[q][rr] + bb);
    }
    __syncthreads();

    gemm44(Wl, HID_, HID_ / 32, R1, HID_, sW, tid, v);
    #pragma unroll
    for (int q = 0; q < 4; q++) {
        int j = jt + (q << 6);
        #pragma unroll
        for (int rr = 0; rr < 4; rr++) {
            int b = b0 + rg * 4 + rr;
            out[((size_t)b * WIN_ + step) * HID_ + j] = v[q][rr];
        }
    }
}

// ============ SERIAL PHASE: persistent weight-resident kernel ============
// grid = 64 CTAs (8 j-slices x 8 row-slices), all resident. W slice in smem once.

// stage x chunk: 64 rows x 32 k, one float4 per thread, cp.async.cg (L1 bypass)
__device__ __forceinline__ void s_stage_x(int layer, int s, int step, int row0,
                                          int ch, float* dst, int tid) {
    int r  = tid >> 3;       // local row 0..63
    int c4 = tid & 7;
    int k  = (ch << 5) + (c4 << 2);
    uint32_t d = (uint32_t)__cvta_generic_to_shared(dst + r * 32 + (c4 << 2));
    const float* src;
    int sz = 16;
    if (layer == 0) {
        if (k < HID_)      src = g_lastall[s] + (size_t)(row0 + r) * HID_ + k;
        else if (k < K1_)  src = g_ls + ((size_t)step * B_ + row0 + r) * LOGSIG_ + (k - HID_);
        else             { src = g_ls; sz = 0; }
    } else if (layer == 1) {
        src = g_h1 + (size_t)(row0 + r) * HID_ + k;
    } else {
        src = g_h2 + (size_t)(row0 + r) * HID_ + k;
    }
    asm volatile("cp.async.cg.shared.global [%0], [%1], 16, %2;"
                 :: "r"(d), "l"(src), "r"(sz));
    asm volatile("cp.async.commit_group;");
}

// one layer GEMM: W resident in sW tiles [tile0..tile0+nch), x double-buffered
__device__ __forceinline__ void s_layer(int layer, int nch, int tile0,
                                        int s, int step, int row0,
                                        const float* __restrict__ sW,
                                        float* __restrict__ sX,
                                        int tid, int jl, int rg, float outv[4]) {
    unsigned long long acc[4] = {0ULL, 0ULL, 0ULL, 0ULL};
    s_stage_x(layer, s, step, row0, 0, sX, tid);
    for (int ch = 0; ch < nch; ch++) {
        if (ch + 1 < nch) {
            s_stage_x(layer, s, step, row0, ch + 1, sX + ((ch + 1) & 1) * 2048, tid);
            asm volatile("cp.async.wait_group 1;");
        } else {
            asm volatile("cp.async.wait_group 0;");
        }
        __syncthreads();
        const float* xt = sX + (ch & 1) * 2048;
        const float* wt = sW + (tile0 + ch) * 1024;
        ulonglong2 w2[8];
        #pragma unroll
        for (int c4 = 0; c4 < 8; c4++)
            w2[c4] = *reinterpret_cast<const ulonglong2*>(
                wt + jl * 32 + ((c4 ^ (jl & 7)) << 2));
        #pragma unroll
        for (int r = 0; r < 4; r++) {
            const float* xr = xt + ((rg << 2) + r) * 32;
            #pragma unroll
            for (int c4 = 0; c4 < 8; c4++) {
                ulonglong2 x2 = *reinterpret_cast<const ulonglong2*>(xr + (c4 << 2));
                ffma2(acc[r], w2[c4].x, x2.x);
                ffma2(acc[r], w2[c4].y, x2.y);
            }
        }
        __syncthreads();
    }
    #pragma unroll
    for (int r = 0; r < 4; r++) {
        float lo = __uint_as_float((unsigned)acc[r]);
        float hi = __uint_as_float((unsigned)(acc[r] >> 32));
        outv[r] = lo + hi;
    }
}

// grid-wide barrier: all 64 CTAs resident by construction.
__device__ __forceinline__ void gbar(int target) {
    __threadfence();
    __syncthreads();
    if (threadIdx.x == 0) {
        atomicAdd(&g_barcnt, 1);
        while (atomicAdd(&g_barcnt, 0) < target) { }
    }
    __syncthreads();
}

__global__ void __launch_bounds__(512, 1)
serial_persist_kernel(const float* __restrict__ W1, const float* __restrict__ b1,
                      const float* __restrict__ W2, const float* __restrict__ b2,
                      const float* __restrict__ W3, const float* __restrict__ b3)
{
    extern __shared__ float smem[];
    float* sW = smem;                       // 29 tiles x 32j x 32k (swizzled)
    float* sX = sW + S_TILES_ * 1024;       // 2 x (64 x 32)

    const int tid = threadIdx.x;
    const int jl  = tid & 31;
    const int rg  = tid >> 5;               // 0..15, 4 rows each
    const int jg  = blockIdx.x & 7;
    const int rb  = blockIdx.x >> 3;
    const int j   = (jg << 5) + jl;
    const int row0 = rb << 6;               // 64 rows per CTA

    const float bb1 = b1[j], bb2 = b2[j], bb3 = b3[j];

    // ---- load W slices (once), swizzled: tile t, row r(j_local), float4 c4 ----
    for (int idx = tid; idx < S_TILES_ * 256; idx += 512) {
        int t   = idx >> 8;
        int w   = idx & 255;
        int r   = w >> 3;
        int c4  = w & 7;
        const float* Wg; int K; int kq;
        if (t < 13)      { Wg = W1; K = K1_;  kq = t; }
        else if (t < 21) { Wg = W2; K = HID_; kq = t - 13; }
        else             { Wg = W3; K = HID_; kq = t - 21; }
        int k = (kq << 5) + (c4 << 2);
        float4 v = make_float4(0.f, 0.f, 0.f, 0.f);
        if (k + 4 <= K)
            v = *reinterpret_cast<const float4*>(Wg + (size_t)((jg << 5) + r) * K + k);
        *reinterpret_cast<float4*>(sW + t * 1024 + r * 32 + ((c4 ^ (r & 7)) << 2)) = v;
    }
    __syncthreads();

    const int nupd = g_nupd;                // 21
    int bar = 0;
    for (int si = 0; si < nupd; si++) {
        const int step = g_ustep[si];
        float v[4];

        s_layer(0, 13, 0, si, step, row0, sW, sX, tid, jl, rg, v);
        #pragma unroll
        for (int r = 0; r < 4; r++)
            g_h1[(size_t)(row0 + (rg << 2) + r) * HID_ + j] = fmaxf(v[r] + bb1, 0.f);
        bar += 64; gbar(bar);

        s_layer(1, 8, 13, si, step, row0, sW, sX, tid, jl, rg, v);
        #pragma unroll
        for (int r = 0; r < 4; r++)
            g_h2[(size_t)(row0 + (rg << 2) + r) * HID_ + j] = fmaxf(v[r] + bb2, 0.f);
        bar += 64; gbar(bar);

        s_layer(2, 8, 21, si, step, row0, sW, sX, tid, jl, rg, v);
        #pragma unroll
        for (int r = 0; r < 4; r++)
            g_lastall[si + 1][(size_t)(row0 + (rg << 2) + r) * HID_ + j] = tanhf(v[r] + bb3);
        if (si + 1 < nupd) { bar += 64; gbar(bar); }
    }
}

extern "C" void kernel_launch(void* const* d_in, const int* in_sizes, int n_in,
                              void* d_out, int out_size) {
    (void)in_sizes; (void)n_in; (void)out_size;
    const float* z  = (const float*)d_in[0];
    const float* W1 = (const float*)d_in[1];
    const float* b1 = (const float*)d_in[2];
    const float* W2 = (const float*)d_in[3];
    const float* b2 = (const float*)d_in[4];
    const float* W3 = (const float*)d_in[5];
    const float* b3 = (const float*)d_in[6];
    const float* Wl = (const float*)d_in[7];
    float* out = (float*)d_out;

    const size_t smem_par =
        (2 * WTS_ + BT_ * K1P_ + BT_ * HID_) * sizeof(float);     // ~108 KB
    const size_t smem_ser =
        (S_TILES_ * 1024 + 2 * 2048) * sizeof(float);             // ~132 KB
    cudaFuncSetAttribute(rnn_all_kernel,
                         cudaFuncAttributeMaxDynamicSharedMemorySize, (int)smem_par);
    cudaFuncSetAttribute(serial_persist_kernel,
                         cudaFuncAttributeMaxDynamicSharedMemorySize, (int)smem_ser);

    sched_kernel<<<1, 256>>>();
    zero_last_kernel<<<(B_ * HID_ + 255) / 256, 256>>>();
    cumsum_part_kernel<<<(B_ * NCH_ * 4) / 256, 256>>>(z);
    cumsum_write_kernel<<<(B_ * NCH_ * 4) / 256, 256>>>(z);
    logsig_kernel<<<dim3(WIN_, B_), 160>>>();

    serial_persist_kernel<<<64, 512, smem_ser>>>(W1, b1, W2, b2, W3, b3);

    rnn_all_kernel<<<WIN_ * (B_ / BT_), 256, smem_par>>>(
        W1, b1, W2, b2, W3, b3, Wl, out);
}

// round 10
// speedup vs baseline: 1.3567x; 1.2488x over previous
#include <cuda_runtime.h>
#include <math.h>
#include <stdint.h>

constexpr int B_    = 512;
constexpr int LEN_  = 1000;
constexpr int D_    = 16;
constexpr int HID_  = 256;
constexpr int WIN_  = 64;
constexpr int PAIRS_  = 120;
constexpr int LOGSIG_ = 136;
constexpr int K1_   = HID_ + LOGSIG_;   // 392
constexpr int K1P_  = 416;              // 13*32
constexpr int BT_   = 16;               // rows per CTA (parallel phase)
constexpr int NCH_  = 32;               // cumsum time chunks
constexpr int WTS_  = 256 * 32;         // swizzled W tile (floats), parallel
constexpr int S_TILES_ = 13 + 8 + 8;    // serial W chunk-tiles (29)
constexpr int SGRID_ = 128;             // serial CTAs (16 row-slices x 8 j-slices)
constexpr int SROWS_ = 32;              // rows per serial CTA

__device__ float g_X[(size_t)B_ * LEN_ * D_];
__device__ float g_ls[(size_t)WIN_ * B_ * LOGSIG_];
__device__ float g_lastall[24][(size_t)B_ * HID_];
__device__ float g_h1[(size_t)B_ * HID_];
__device__ float g_h2[(size_t)B_ * HID_];
__device__ float g_part[(size_t)B_ * NCH_ * D_];
__device__ float g_dts[LEN_ - 1];
__device__ int   g_tidx[WIN_ - 1];
__device__ int   g_sidx[WIN_ - 1];
__device__ int   g_seg[WIN_];
__device__ int   g_updflag[WIN_];
__device__ int   g_ustep[WIN_];
__device__ int   g_nupd;
__device__ int   g_barcnt;
__device__ int   g_iu[PAIRS_];
__device__ int   g_ju[PAIRS_];

__host__ __device__ __forceinline__ double tb_d(int i) {
    return (i == LEN_ - 1) ? 1.0 : (double)i * (1.0 / 999.0);
}
__host__ __device__ __forceinline__ double tt_d(int k) {
    return (k == WIN_ - 1) ? 1.0 : (double)k * (1.0 / 63.0);
}

__host__ __device__ inline void compute_upd(bool upd[WIN_]) {
    double tu[20];
    for (int j = 0; j < 20; j++) tu[j] = tb_d(50 * j);
    int u_idx[63];
    for (int k = 1; k < 64; k++) {
        double t = tt_d(k);
        int uj = 0;
        for (int j = 0; j < 20; j++) if (tu[j] <= t) uj = j;
        u_idx[k - 1] = uj;
    }
    double qt[64]; int qn = 0, last = -1;
    for (int k = 0; k < 63; k++) {
        int iu = u_idx[k] < 0 ? 0 : u_idx[k];
        if (iu != last) { qt[qn++] = tu[iu]; last = iu; }
    }
    qt[qn++] = tt_d(63);
    int qh = 0;
    for (int i = 0; i < 64; i++) {
        upd[i] = false;
        if (qh < qn && tt_d(i) >= qt[qh]) { qh++; upd[i] = true; }
    }
}

__global__ void sched_kernel() {
    int tid = threadIdx.x;
    for (int i = tid; i < LEN_ - 1; i += blockDim.x)
        g_dts[i] = sqrtf((float)(tb_d(i + 1) - tb_d(i)));
    if (tid < WIN_ - 1) {
        double t = tt_d(tid + 1);
        int ti = 0;
        for (int i = 0; i < LEN_; i++) if (tb_d(i) <= t) ti = i;
        g_tidx[tid] = ti;
        int uj = 0;
        for (int j = 0; j < LEN_ / 50; j++) if (tb_d(50 * j) <= t) uj = j;
        g_sidx[tid] = 50 * uj;
    }
    if (tid >= 64 && tid < 64 + PAIRS_) {
        int p = tid - 64;
        int i = 0, accp = 0;
        while (accp + (D_ - 1 - i) <= p) { accp += D_ - 1 - i; i++; }
        g_iu[p] = i;
        g_ju[p] = i + 1 + (p - accp);
    }
    if (tid == 0) {
        bool upd[WIN_];
        compute_upd(upd);
        int s = 0;
        for (int i = 0; i < WIN_; i++) {
            g_seg[i] = s;
            g_updflag[i] = upd[i] ? 1 : 0;
            if (upd[i]) { g_ustep[s] = i; s++; }
        }
        g_nupd = s;
    }
}

__global__ void zero_last_kernel() {
    int g = blockIdx.x * blockDim.x + threadIdx.x;
    if (g < B_ * HID_) g_lastall[0][g] = 0.f;
    if (g == 0) g_barcnt = 0;
}

__device__ __forceinline__ void chunk_rng(int c, int& t0, int& t1) {
    t0 = (c * 999) / NCH_ + 1;
    t1 = ((c + 1) * 999) / NCH_;
}

__global__ void cumsum_part_kernel(const float* __restrict__ z) {
    int g = blockIdx.x * blockDim.x + threadIdx.x;
    int d4 = g & 3, c = (g >> 2) & (NCH_ - 1), b = g >> 7;
    int t0, t1; chunk_rng(c, t0, t1);
    const float4* zp = reinterpret_cast<const float4*>(z + (size_t)b * LEN_ * D_) + d4;
    float4 s = make_float4(0.f, 0.f, 0.f, 0.f);
    for (int t = t0; t <= t1; t++) {
        float dt = g_dts[t - 1];
        float4 zv = zp[t * 4];
        s.x += zv.x * dt; s.y += zv.y * dt; s.z += zv.z * dt; s.w += zv.w * dt;
    }
    reinterpret_cast<float4*>(g_part + ((size_t)b * NCH_ + c) * D_)[d4] = s;
}

__global__ void cumsum_write_kernel(const float* __restrict__ z) {
    int g = blockIdx.x * blockDim.x + threadIdx.x;
    int d4 = g & 3, c = (g >> 2) & (NCH_ - 1), b = g >> 7;
    float4 acc = make_float4(0.f, 0.f, 0.f, 0.f);
    for (int cc = 0; cc < c; cc++) {
        float4 p = reinterpret_cast<const float4*>(g_part + ((size_t)b * NCH_ + cc) * D_)[d4];
        acc.x += p.x; acc.y += p.y; acc.z += p.z; acc.w += p.w;
    }
    int t0, t1; chunk_rng(c, t0, t1);
    const float4* zp = reinterpret_cast<const float4*>(z + (size_t)b * LEN_ * D_) + d4;
    float4* xp = reinterpret_cast<float4*>(g_X + (size_t)b * LEN_ * D_) + d4;
    if (c == 0) xp[0] = make_float4(0.f, 0.f, 0.f, 0.f);
    for (int t = t0; t <= t1; t++) {
        float dt = g_dts[t - 1];
        float4 zv = zp[t * 4];
        acc.x += zv.x * dt; acc.y += zv.y * dt; acc.z += zv.z * dt; acc.w += zv.w * dt;
        xp[t * 4] = acc;
    }
}

__global__ void logsig_kernel() {
    int kk = blockIdx.x, b = blockIdx.y, tid = threadIdx.x;
    if (kk == 0) {
        if (tid < LOGSIG_) g_ls[(size_t)b * LOGSIG_ + tid] = 0.f;
        return;
    }
    int k = kk - 1, t1 = g_tidx[k], s0 = g_sidx[k];
    int nrow = t1 - s0 + 1;                          // <= 50
    __shared__ float sX[50 * 16];
    const float* xb = g_X + ((size_t)b * LEN_ + s0) * D_;
    for (int e = tid; e < (nrow * D_) >> 2; e += blockDim.x)
        reinterpret_cast<float4*>(sX)[e] = reinterpret_cast<const float4*>(xb)[e];
    __syncthreads();
    float* outp = g_ls + ((size_t)kk * B_ + b) * LOGSIG_;
    if (tid < D_) {
        outp[tid] = sX[(t1 - s0) * D_ + tid];
    } else if (tid < LOGSIG_) {
        int p = tid - D_, iu = g_iu[p], ju = g_ju[p];
        float xi = sX[iu], xj = sX[ju];
        float acc = 0.f;
        for (int s = 1; s < nrow; s++) {
            float yi = sX[s * D_ + iu], yj = sX[s * D_ + ju];
            acc += xi * (yj - xj) - xj * (yi - xi);
            xi = yi; xj = yj;
        }
        outp[tid] = 0.5f * acc;
    }
}

__device__ __forceinline__ void ffma2(unsigned long long& acc,
                                      unsigned long long a, unsigned long long b) {
    asm("fma.rn.f32x2 %0, %1, %2, %0;" : "+l"(acc) : "l"(a), "l"(b));
}

// ============ PARALLEL PHASE (R8 machinery + update-step skip) ============

__device__ __forceinline__ void stage_sw256(const float* __restrict__ Wg, int Ktrue,
                                            int k0, float* sWbuf, int tid) {
    #pragma unroll
    for (int u = 0; u < 8; u++) {
        int g = (u << 8) + tid;
        int row = g >> 3;
        int c4  = g & 7;
        int k   = k0 + (c4 << 2);
        uint32_t dst = (uint32_t)__cvta_generic_to_shared(
            sWbuf + row * 32 + ((c4 ^ (row & 7)) << 2));
        bool valid = (k + 4 <= Ktrue);
        const float* src = valid ? (Wg + (size_t)row * Ktrue + k) : Wg;
        int sz = valid ? 16 : 0;
        asm volatile("cp.async.cg.shared.global [%0], [%1], 16, %2;"
                     :: "r"(dst), "l"(src), "r"(sz));
    }
    asm volatile("cp.async.commit_group;");
}

__device__ __forceinline__ void gemm44(
    const float* __restrict__ Wg, int Ktrue, int nch,
    const float* __restrict__ sin, int sstride,
    float* __restrict__ sW, int tid, float outv[4][4])
{
    const int jt = tid & 63;
    const int rg = tid >> 6;
    const int lane = tid & 31;

    unsigned long long acc[4][4];
    #pragma unroll
    for (int q = 0; q < 4; q++)
        #pragma unroll
        for (int r = 0; r < 4; r++) acc[q][r] = 0ULL;

    stage_sw256(Wg, Ktrue, 0, sW, tid);
    for (int ch = 0; ch < nch; ch++) {
        if (ch + 1 < nch) {
            stage_sw256(Wg, Ktrue, (ch + 1) << 5, sW + ((ch + 1) & 1) * WTS_, tid);
            asm volatile("cp.async.wait_group 1;");
        } else {
            asm volatile("cp.async.wait_group 0;");
        }
        __syncthreads();
        const float* cur = sW + (ch & 1) * WTS_;
        const int k0 = ch << 5;

        ulonglong2 xs = *reinterpret_cast<const ulonglong2*>(
            sin + (rg * 4 + (lane >> 3)) * sstride + k0 + ((lane & 7) << 2));

        #pragma unroll
        for (int c4 = 0; c4 < 8; c4++) {
            ulonglong2 wv[4];
            #pragma unroll
            for (int q = 0; q < 4; q++) {
                int row = jt + (q << 6);
                wv[q] = *reinterpret_cast<const ulonglong2*>(
                    cur + row * 32 + ((c4 ^ (row & 7)) << 2));
            }
            #pragma unroll
            for (int rr = 0; rr < 4; rr++) {
                const int src = (rr << 3) + c4;
                unsigned long long xa = __shfl_sync(0xffffffffu, xs.x, src);
                unsigned long long xb = __shfl_sync(0xffffffffu, xs.y, src);
                #pragma unroll
                for (int q = 0; q < 4; q++) {
                    ffma2(acc[q][rr], wv[q].x, xa);
                    ffma2(acc[q][rr], wv[q].y, xb);
                }
            }
        }
        __syncthreads();
    }
    #pragma unroll
    for (int q = 0; q < 4; q++)
        #pragma unroll
        for (int r = 0; r < 4; r++) {
            float lo = __uint_as_float((unsigned)acc[q][r]);
            float hi = __uint_as_float((unsigned)(acc[q][r] >> 32));
            outv[q][r] = lo + hi;
        }
}

__global__ void __launch_bounds__(256, 2)
rnn_all_kernel(const float* __restrict__ W1, const float* __restrict__ b1,
               const float* __restrict__ W2, const float* __restrict__ b2,
               const float* __restrict__ W3, const float* __restrict__ b3,
               const float* __restrict__ Wl, float* __restrict__ out)
{
    extern __shared__ float smem[];
    float* sW = smem;                       // 2 * 256*32 swizzled
    float* R0 = sW + 2 * WTS_;              // 16*416
    float* R1 = R0 + BT_ * K1P_;            // 16*256

    const int tid  = threadIdx.x;
    const int jt   = tid & 63;
    const int rg   = tid >> 6;
    const int step = blockIdx.x >> 5;       // 32 CTAs per step
    const int b0   = (blockIdx.x & 31) * BT_;

    float v[4][4];

    if (g_updflag[step]) {
        // h for this step was computed in the serial phase: load and apply Wl.
        const float* hsrc = g_lastall[g_seg[step] + 1];
        for (int r = 0; r < BT_; r++) {
            int b = b0 + r;
            for (int c = tid; c < HID_; c += 256)
                R1[r * HID_ + c] = hsrc[(size_t)b * HID_ + c];
        }
        // gemm44's internal __syncthreads orders these writes before reads.
    } else {
        const float* last_in = g_lastall[g_seg[step]];
        for (int r = 0; r < BT_; r++) {
            int b = b0 + r;
            for (int c = tid; c < K1P_; c += 256) {
                float vv = 0.f;
                if (c < HID_)     vv = last_in[(size_t)b * HID_ + c];
                else if (c < K1_) vv = g_ls[((size_t)step * B_ + b) * LOGSIG_ + (c - HID_)];
                R0[r * K1P_ + c] = vv;
            }
        }

        gemm44(W1, K1_, K1P_ / 32, R0, K1P_, sW, tid, v);
        #pragma unroll
        for (int q = 0; q < 4; q++) {
            int j = jt + (q << 6); float bb = b1[j];
            #pragma unroll
            for (int rr = 0; rr < 4; rr++)
                R1[(rg * 4 + rr) * HID_ + j] = fmaxf(v[q][rr] + bb, 0.f);
        }
        __syncthreads();

        gemm44(W2, HID_, HID_ / 32, R1, HID_, sW, tid, v);
        __syncthreads();
        #pragma unroll
        for (int q = 0; q < 4; q++) {
            int j = jt + (q << 6); float bb = b2[j];
            #pragma unroll
            for (int rr = 0; rr < 4; rr++)
                R0[(rg * 4 + rr) * HID_ + j] = fmaxf(v[q][rr] + bb, 0.f);
        }
        __syncthreads();

        gemm44(W3, HID_, HID_ / 32, R0, HID_, sW, tid, v);
        __syncthreads();
        #pragma unroll
        for (int q = 0; q < 4; q++) {
            int j = jt + (q << 6); float bb = b3[j];
            #pragma unroll
            for (int rr = 0; rr < 4; rr++)
                R1[(rg * 4 + rr) * HID_ + j] = tanhf(v[q][rr] + bb);
        }
        __syncthreads();
    }

    gemm44(Wl, HID_, HID_ / 32, R1, HID_, sW, tid, v);
    #pragma unroll
    for (int q = 0; q < 4; q++) {
        int j = jt + (q << 6);
        #pragma unroll
        for (int rr = 0; rr < 4; rr++) {
            int b = b0 + rg * 4 + rr;
            out[((size_t)b * WIN_ + step) * HID_ + j] = v[q][rr];
        }
    }
}

// ============ SERIAL PHASE: persistent weight-resident kernel (128 CTAs) ============
// grid = 128 CTAs (8 j-slices x 16 row-slices of 32 rows), all resident.

__device__ __forceinline__ void s_stage_x(int layer, int s, int step, int row0,
                                          int ch, float* dst, int tid) {
    if (tid < 256) {
        int r  = tid >> 3;       // local row 0..31
        int c4 = tid & 7;
        int k  = (ch << 5) + (c4 << 2);
        uint32_t d = (uint32_t)__cvta_generic_to_shared(dst + r * 32 + (c4 << 2));
        const float* src;
        int sz = 16;
        if (layer == 0) {
            if (k < HID_)      src = g_lastall[s] + (size_t)(row0 + r) * HID_ + k;
            else if (k < K1_)  src = g_ls + ((size_t)step * B_ + row0 + r) * LOGSIG_ + (k - HID_);
            else             { src = g_ls; sz = 0; }
        } else if (layer == 1) {
            src = g_h1 + (size_t)(row0 + r) * HID_ + k;
        } else {
            src = g_h2 + (size_t)(row0 + r) * HID_ + k;
        }
        asm volatile("cp.async.cg.shared.global [%0], [%1], 16, %2;"
                     :: "r"(d), "l"(src), "r"(sz));
    }
    asm volatile("cp.async.commit_group;");
}

// one layer GEMM: W resident in sW tiles, x (32 rows) double-buffered
__device__ __forceinline__ void s_layer(int layer, int nch, int tile0,
                                        int s, int step, int row0,
                                        const float* __restrict__ sW,
                                        float* __restrict__ sX,
                                        int tid, int jl, int rg, float outv[2]) {
    unsigned long long acc[2] = {0ULL, 0ULL};
    s_stage_x(layer, s, step, row0, 0, sX, tid);
    for (int ch = 0; ch < nch; ch++) {
        if (ch + 1 < nch) {
            s_stage_x(layer, s, step, row0, ch + 1, sX + ((ch + 1) & 1) * 1024, tid);
            asm volatile("cp.async.wait_group 1;");
        } else {
            asm volatile("cp.async.wait_group 0;");
        }
        __syncthreads();
        const float* xt = sX + (ch & 1) * 1024;
        const float* wt = sW + (tile0 + ch) * 1024;
        ulonglong2 w2[8];
        #pragma unroll
        for (int c4 = 0; c4 < 8; c4++)
            w2[c4] = *reinterpret_cast<const ulonglong2*>(
                wt + jl * 32 + ((c4 ^ (jl & 7)) << 2));
        #pragma unroll
        for (int r = 0; r < 2; r++) {
            const float* xr = xt + ((rg << 1) + r) * 32;
            #pragma unroll
            for (int c4 = 0; c4 < 8; c4++) {
                ulonglong2 x2 = *reinterpret_cast<const ulonglong2*>(xr + (c4 << 2));
                ffma2(acc[r], w2[c4].x, x2.x);
                ffma2(acc[r], w2[c4].y, x2.y);
            }
        }
        __syncthreads();
    }
    #pragma unroll
    for (int r = 0; r < 2; r++) {
        float lo = __uint_as_float((unsigned)acc[r]);
        float hi = __uint_as_float((unsigned)(acc[r] >> 32));
        outv[r] = lo + hi;
    }
}

// grid-wide barrier: arrive via one atomic, poll via plain acquire loads (no
// atomic-ALU serialization on the poll path). All 128 CTAs resident.
__device__ __forceinline__ void gbar(int target) {
    __threadfence();
    __syncthreads();
    if (threadIdx.x == 0) {
        atomicAdd(&g_barcnt, 1);
        int v;
        do {
            asm volatile("ld.global.acquire.gpu.b32 %0, [%1];"
                         : "=r"(v) : "l"(&g_barcnt));
        } while (v < target);
    }
    __syncthreads();
}

__global__ void __launch_bounds__(512, 1)
serial_persist_kernel(const float* __restrict__ W1, const float* __restrict__ b1,
                      const float* __restrict__ W2, const float* __restrict__ b2,
                      const float* __restrict__ W3, const float* __restrict__ b3)
{
    extern __shared__ float smem[];
    float* sW = smem;                       // 29 tiles x 32j x 32k (swizzled)
    float* sX = sW + S_TILES_ * 1024;       // 2 x (32 x 32)

    const int tid = threadIdx.x;
    const int jl  = tid & 31;
    const int rg  = tid >> 5;               // 0..15, 2 rows each
    const int jg  = blockIdx.x & 7;
    const int rb  = blockIdx.x >> 3;        // 0..15
    const int j   = (jg << 5) + jl;
    const int row0 = rb * SROWS_;           // 32 rows per CTA

    const float bb1 = b1[j], bb2 = b2[j], bb3 = b3[j];

    // ---- load W slices (once), swizzled ----
    for (int idx = tid; idx < S_TILES_ * 256; idx += 512) {
        int t   = idx >> 8;
        int w   = idx & 255;
        int r   = w >> 3;
        int c4  = w & 7;
        const float* Wg; int K; int kq;
        if (t < 13)      { Wg = W1; K = K1_;  kq = t; }
        else if (t < 21) { Wg = W2; K = HID_; kq = t - 13; }
        else             { Wg = W3; K = HID_; kq = t - 21; }
        int k = (kq << 5) + (c4 << 2);
        float4 v = make_float4(0.f, 0.f, 0.f, 0.f);
        if (k + 4 <= K)
            v = *reinterpret_cast<const float4*>(Wg + (size_t)((jg << 5) + r) * K + k);
        *reinterpret_cast<float4*>(sW + t * 1024 + r * 32 + ((c4 ^ (r & 7)) << 2)) = v;
    }
    __syncthreads();

    const int nupd = g_nupd;                // 21
    int bar = 0;
    for (int si = 0; si < nupd; si++) {
        const int step = g_ustep[si];
        float v[2];

        s_layer(0, 13, 0, si, step, row0, sW, sX, tid, jl, rg, v);
        #pragma unroll
        for (int r = 0; r < 2; r++)
            g_h1[(size_t)(row0 + (rg << 1) + r) * HID_ + j] = fmaxf(v[r] + bb1, 0.f);
        bar += SGRID_; gbar(bar);

        s_layer(1, 8, 13, si, step, row0, sW, sX, tid, jl, rg, v);
        #pragma unroll
        for (int r = 0; r < 2; r++)
            g_h2[(size_t)(row0 + (rg << 1) + r) * HID_ + j] = fmaxf(v[r] + bb2, 0.f);
        bar += SGRID_; gbar(bar);

        s_layer(2, 8, 21, si, step, row0, sW, sX, tid, jl, rg, v);
        #pragma unroll
        for (int r = 0; r < 2; r++)
            g_lastall[si + 1][(size_t)(row0 + (rg << 1) + r) * HID_ + j] = tanhf(v[r] + bb3);
        if (si + 1 < nupd) { bar += SGRID_; gbar(bar); }
    }
}

extern "C" void kernel_launch(void* const* d_in, const int* in_sizes, int n_in,
                              void* d_out, int out_size) {
    (void)in_sizes; (void)n_in; (void)out_size;
    const float* z  = (const float*)d_in[0];
    const float* W1 = (const float*)d_in[1];
    const float* b1 = (const float*)d_in[2];
    const float* W2 = (const float*)d_in[3];
    const float* b2 = (const float*)d_in[4];
    const float* W3 = (const float*)d_in[5];
    const float* b3 = (const float*)d_in[6];
    const float* Wl = (const float*)d_in[7];
    float* out = (float*)d_out;

    const size_t smem_par =
        (2 * WTS_ + BT_ * K1P_ + BT_ * HID_) * sizeof(float);     // ~108 KB
    const size_t smem_ser =
        (S_TILES_ * 1024 + 2 * 1024) * sizeof(float);             // ~124 KB
    cudaFuncSetAttribute(rnn_all_kernel,
                         cudaFuncAttributeMaxDynamicSharedMemorySize, (int)smem_par);
    cudaFuncSetAttribute(serial_persist_kernel,
                         cudaFuncAttributeMaxDynamicSharedMemorySize, (int)smem_ser);

    sched_kernel<<<1, 256>>>();
    zero_last_kernel<<<(B_ * HID_ + 255) / 256, 256>>>();
    cumsum_part_kernel<<<(B_ * NCH_ * 4) / 256, 256>>>(z);
    cumsum_write_kernel<<<(B_ * NCH_ * 4) / 256, 256>>>(z);
    logsig_kernel<<<dim3(WIN_, B_), 160>>>();

    serial_persist_kernel<<<SGRID_, 512, smem_ser>>>(W1, b1, W2, b2, W3, b3);

    rnn_all_kernel<<<WIN_ * (B_ / BT_), 256, smem_par>>>(
        W1, b1, W2, b2, W3, b3, Wl, out);
}

// round 12
// speedup vs baseline: 1.4127x; 1.0412x over previous
#include <cuda_runtime.h>
#include <math.h>
#include <stdint.h>

constexpr int B_    = 512;
constexpr int LEN_  = 1000;
constexpr int D_    = 16;
constexpr int HID_  = 256;
constexpr int WIN_  = 64;
constexpr int PAIRS_  = 120;
constexpr int LOGSIG_ = 136;
constexpr int K1_   = HID_ + LOGSIG_;   // 392
constexpr int K1P_  = 416;              // 13*32
constexpr int BT_   = 16;               // rows per CTA (parallel phase)
constexpr int NCH_  = 32;               // cumsum time chunks
constexpr int WTS_  = 256 * 32;         // swizzled W tile (floats), parallel
constexpr int S_TILES_ = 13 + 8 + 8;    // serial W chunk-tiles (29)
constexpr int SGRID_ = 128;             // serial CTAs (8 j-slices x 16 row-slices)
constexpr int SROWS_ = 32;              // rows per serial CTA
constexpr int SXF_   = SROWS_ * K1P_;   // serial x stage floats (13312)

__device__ float g_X[(size_t)B_ * LEN_ * D_];
__device__ float g_ls[(size_t)WIN_ * B_ * LOGSIG_];
__device__ float g_lastall[24][(size_t)B_ * HID_];
__device__ float g_h1[(size_t)B_ * HID_];
__device__ float g_h2[(size_t)B_ * HID_];
__device__ float g_part[(size_t)B_ * NCH_ * D_];
__device__ float g_dts[LEN_ - 1];
__device__ int   g_tidx[WIN_ - 1];
__device__ int   g_sidx[WIN_ - 1];
__device__ int   g_seg[WIN_];
__device__ int   g_updflag[WIN_];
__device__ int   g_ustep[WIN_];
__device__ int   g_nupd;
__device__ int   g_barcnt;
__device__ int   g_iu[PAIRS_];
__device__ int   g_ju[PAIRS_];

__host__ __device__ __forceinline__ double tb_d(int i) {
    return (i == LEN_ - 1) ? 1.0 : (double)i * (1.0 / 999.0);
}
__host__ __device__ __forceinline__ double tt_d(int k) {
    return (k == WIN_ - 1) ? 1.0 : (double)k * (1.0 / 63.0);
}

__host__ __device__ inline void compute_upd(bool upd[WIN_]) {
    double tu[20];
    for (int j = 0; j < 20; j++) tu[j] = tb_d(50 * j);
    int u_idx[63];
    for (int k = 1; k < 64; k++) {
        double t = tt_d(k);
        int uj = 0;
        for (int j = 0; j < 20; j++) if (tu[j] <= t) uj = j;
        u_idx[k - 1] = uj;
    }
    double qt[64]; int qn = 0, last = -1;
    for (int k = 0; k < 63; k++) {
        int iu = u_idx[k] < 0 ? 0 : u_idx[k];
        if (iu != last) { qt[qn++] = tu[iu]; last = iu; }
    }
    qt[qn++] = tt_d(63);
    int qh = 0;
    for (int i = 0; i < 64; i++) {
        upd[i] = false;
        if (qh < qn && tt_d(i) >= qt[qh]) { qh++; upd[i] = true; }
    }
}

__global__ void sched_kernel() {
    int tid = threadIdx.x;
    for (int i = tid; i < LEN_ - 1; i += blockDim.x)
        g_dts[i] = sqrtf((float)(tb_d(i + 1) - tb_d(i)));
    if (tid < WIN_ - 1) {
        double t = tt_d(tid + 1);
        int ti = 0;
        for (int i = 0; i < LEN_; i++) if (tb_d(i) <= t) ti = i;
        g_tidx[tid] = ti;
        int uj = 0;
        for (int j = 0; j < LEN_ / 50; j++) if (tb_d(50 * j) <= t) uj = j;
        g_sidx[tid] = 50 * uj;
    }
    if (tid >= 64 && tid < 64 + PAIRS_) {
        int p = tid - 64;
        int i = 0, accp = 0;
        while (accp + (D_ - 1 - i) <= p) { accp += D_ - 1 - i; i++; }
        g_iu[p] = i;
        g_ju[p] = i + 1 + (p - accp);
    }
    if (tid == 0) {
        bool upd[WIN_];
        compute_upd(upd);
        int s = 0;
        for (int i = 0; i < WIN_; i++) {
            g_seg[i] = s;
            g_updflag[i] = upd[i] ? 1 : 0;
            if (upd[i]) { g_ustep[s] = i; s++; }
        }
        g_nupd = s;
    }
}

__global__ void zero_last_kernel() {
    int g = blockIdx.x * blockDim.x + threadIdx.x;
    if (g < B_ * HID_) g_lastall[0][g] = 0.f;
    if (g == 0) g_barcnt = 0;
}

__device__ __forceinline__ void chunk_rng(int c, int& t0, int& t1) {
    t0 = (c * 999) / NCH_ + 1;
    t1 = ((c + 1) * 999) / NCH_;
}

__global__ void cumsum_part_kernel(const float* __restrict__ z) {
    int g = blockIdx.x * blockDim.x + threadIdx.x;
    int d4 = g & 3, c = (g >> 2) & (NCH_ - 1), b = g >> 7;
    int t0, t1; chunk_rng(c, t0, t1);
    const float4* zp = reinterpret_cast<const float4*>(z + (size_t)b * LEN_ * D_) + d4;
    float4 s = make_float4(0.f, 0.f, 0.f, 0.f);
    for (int t = t0; t <= t1; t++) {
        float dt = g_dts[t - 1];
        float4 zv = zp[t * 4];
        s.x += zv.x * dt; s.y += zv.y * dt; s.z += zv.z * dt; s.w += zv.w * dt;
    }
    reinterpret_cast<float4*>(g_part + ((size_t)b * NCH_ + c) * D_)[d4] = s;
}

__global__ void cumsum_write_kernel(const float* __restrict__ z) {
    int g = blockIdx.x * blockDim.x + threadIdx.x;
    int d4 = g & 3, c = (g >> 2) & (NCH_ - 1), b = g >> 7;
    float4 acc = make_float4(0.f, 0.f, 0.f, 0.f);
    for (int cc = 0; cc < c; cc++) {
        float4 p = reinterpret_cast<const float4*>(g_part + ((size_t)b * NCH_ + cc) * D_)[d4];
        acc.x += p.x; acc.y += p.y; acc.z += p.z; acc.w += p.w;
    }
    int t0, t1; chunk_rng(c, t0, t1);
    const float4* zp = reinterpret_cast<const float4*>(z + (size_t)b * LEN_ * D_) + d4;
    float4* xp = reinterpret_cast<float4*>(g_X + (size_t)b * LEN_ * D_) + d4;
    if (c == 0) xp[0] = make_float4(0.f, 0.f, 0.f, 0.f);
    for (int t = t0; t <= t1; t++) {
        float dt = g_dts[t - 1];
        float4 zv = zp[t * 4];
        acc.x += zv.x * dt; acc.y += zv.y * dt; acc.z += zv.z * dt; acc.w += zv.w * dt;
        xp[t * 4] = acc;
    }
}

__global__ void logsig_kernel() {
    int kk = blockIdx.x, b = blockIdx.y, tid = threadIdx.x;
    if (kk == 0) {
        if (tid < LOGSIG_) g_ls[(size_t)b * LOGSIG_ + tid] = 0.f;
        return;
    }
    int k = kk - 1, t1 = g_tidx[k], s0 = g_sidx[k];
    int nrow = t1 - s0 + 1;                          // <= 50
    __shared__ float sX[50 * 16];
    const float* xb = g_X + ((size_t)b * LEN_ + s0) * D_;
    for (int e = tid; e < (nrow * D_) >> 2; e += blockDim.x)
        reinterpret_cast<float4*>(sX)[e] = reinterpret_cast<const float4*>(xb)[e];
    __syncthreads();
    float* outp = g_ls + ((size_t)kk * B_ + b) * LOGSIG_;
    if (tid < D_) {
        outp[tid] = sX[(t1 - s0) * D_ + tid];
    } else if (tid < LOGSIG_) {
        int p = tid - D_, iu = g_iu[p], ju = g_ju[p];
        float xi = sX[iu], xj = sX[ju];
        float acc = 0.f;
        for (int s = 1; s < nrow; s++) {
            float yi = sX[s * D_ + iu], yj = sX[s * D_ + ju];
            acc += xi * (yj - xj) - xj * (yi - xi);
            xi = yi; xj = yj;
        }
        outp[tid] = 0.5f * acc;
    }
}

__device__ __forceinline__ void ffma2(unsigned long long& acc,
                                      unsigned long long a, unsigned long long b) {
    asm("fma.rn.f32x2 %0, %1, %2, %0;" : "+l"(acc) : "l"(a), "l"(b));
}

// ============ PARALLEL PHASE (unchanged from R10) ============

__device__ __forceinline__ void stage_sw256(const float* __restrict__ Wg, int Ktrue,
                                            int k0, float* sWbuf, int tid) {
    #pragma unroll
    for (int u = 0; u < 8; u++) {
        int g = (u << 8) + tid;
        int row = g >> 3;
        int c4  = g & 7;
        int k   = k0 + (c4 << 2);
        uint32_t dst = (uint32_t)__cvta_generic_to_shared(
            sWbuf + row * 32 + ((c4 ^ (row & 7)) << 2));
        bool valid = (k + 4 <= Ktrue);
        const float* src = valid ? (Wg + (size_t)row * Ktrue + k) : Wg;
        int sz = valid ? 16 : 0;
        asm volatile("cp.async.cg.shared.global [%0], [%1], 16, %2;"
                     :: "r"(dst), "l"(src), "r"(sz));
    }
    asm volatile("cp.async.commit_group;");
}

__device__ __forceinline__ void gemm44(
    const float* __restrict__ Wg, int Ktrue, int nch,
    const float* __restrict__ sin, int sstride,
    float* __restrict__ sW, int tid, float outv[4][4])
{
    const int jt = tid & 63;
    const int rg = tid >> 6;
    const int lane = tid & 31;

    unsigned long long acc[4][4];
    #pragma unroll
    for (int q = 0; q < 4; q++)
        #pragma unroll
        for (int r = 0; r < 4; r++) acc[q][r] = 0ULL;

    stage_sw256(Wg, Ktrue, 0, sW, tid);
    for (int ch = 0; ch < nch; ch++) {
        if (ch + 1 < nch) {
            stage_sw256(Wg, Ktrue, (ch + 1) << 5, sW + ((ch + 1) & 1) * WTS_, tid);
            asm volatile("cp.async.wait_group 1;");
        } else {
            asm volatile("cp.async.wait_group 0;");
        }
        __syncthreads();
        const float* cur = sW + (ch & 1) * WTS_;
        const int k0 = ch << 5;

        ulonglong2 xs = *reinterpret_cast<const ulonglong2*>(
            sin + (rg * 4 + (lane >> 3)) * sstride + k0 + ((lane & 7) << 2));

        #pragma unroll
        for (int c4 = 0; c4 < 8; c4++) {
            ulonglong2 wv[4];
            #pragma unroll
            for (int q = 0; q < 4; q++) {
                int row = jt + (q << 6);
                wv[q] = *reinterpret_cast<const ulonglong2*>(
                    cur + row * 32 + ((c4 ^ (row & 7)) << 2));
            }
            #pragma unroll
            for (int rr = 0; rr < 4; rr++) {
                const int src = (rr << 3) + c4;
                unsigned long long xa = __shfl_sync(0xffffffffu, xs.x, src);
                unsigned long long xb = __shfl_sync(0xffffffffu, xs.y, src);
                #pragma unroll
                for (int q = 0; q < 4; q++) {
                    ffma2(acc[q][rr], wv[q].x, xa);
                    ffma2(acc[q][rr], wv[q].y, xb);
                }
            }
        }
        __syncthreads();
    }
    #pragma unroll
    for (int q = 0; q < 4; q++)
        #pragma unroll
        for (int r = 0; r < 4; r++) {
            float lo = __uint_as_float((unsigned)acc[q][r]);
            float hi = __uint_as_float((unsigned)(acc[q][r] >> 32));
            outv[q][r] = lo + hi;
        }
}

__global__ void __launch_bounds__(256, 2)
rnn_all_kernel(const float* __restrict__ W1, const float* __restrict__ b1,
               const float* __restrict__ W2, const float* __restrict__ b2,
               const float* __restrict__ W3, const float* __restrict__ b3,
               const float* __restrict__ Wl, float* __restrict__ out)
{
    extern __shared__ float smem[];
    float* sW = smem;                       // 2 * 256*32 swizzled
    float* R0 = sW + 2 * WTS_;              // 16*416
    float* R1 = R0 + BT_ * K1P_;            // 16*256

    const int tid  = threadIdx.x;
    const int jt   = tid & 63;
    const int rg   = tid >> 6;
    const int step = blockIdx.x >> 5;       // 32 CTAs per step
    const int b0   = (blockIdx.x & 31) * BT_;

    float v[4][4];

    if (g_updflag[step]) {
        const float* hsrc = g_lastall[g_seg[step] + 1];
        for (int r = 0; r < BT_; r++) {
            int b = b0 + r;
            for (int c = tid; c < HID_; c += 256)
                R1[r * HID_ + c] = hsrc[(size_t)b * HID_ + c];
        }
    } else {
        const float* last_in = g_lastall[g_seg[step]];
        for (int r = 0; r < BT_; r++) {
            int b = b0 + r;
            for (int c = tid; c < K1P_; c += 256) {
                float vv = 0.f;
                if (c < HID_)     vv = last_in[(size_t)b * HID_ + c];
                else if (c < K1_) vv = g_ls[((size_t)step * B_ + b) * LOGSIG_ + (c - HID_)];
                R0[r * K1P_ + c] = vv;
            }
        }

        gemm44(W1, K1_, K1P_ / 32, R0, K1P_, sW, tid, v);
        #pragma unroll
        for (int q = 0; q < 4; q++) {
            int j = jt + (q << 6); float bb = b1[j];
            #pragma unroll
            for (int rr = 0; rr < 4; rr++)
                R1[(rg * 4 + rr) * HID_ + j] = fmaxf(v[q][rr] + bb, 0.f);
        }
        __syncthreads();

        gemm44(W2, HID_, HID_ / 32, R1, HID_, sW, tid, v);
        __syncthreads();
        #pragma unroll
        for (int q = 0; q < 4; q++) {
            int j = jt + (q << 6); float bb = b2[j];
            #pragma unroll
            for (int rr = 0; rr < 4; rr++)
                R0[(rg * 4 + rr) * HID_ + j] = fmaxf(v[q][rr] + bb, 0.f);
        }
        __syncthreads();

        gemm44(W3, HID_, HID_ / 32, R0, HID_, sW, tid, v);
        __syncthreads();
        #pragma unroll
        for (int q = 0; q < 4; q++) {
            int j = jt + (q << 6); float bb = b3[j];
            #pragma unroll
            for (int rr = 0; rr < 4; rr++)
                R1[(rg * 4 + rr) * HID_ + j] = tanhf(v[q][rr] + bb);
        }
        __syncthreads();
    }

    gemm44(Wl, HID_, HID_ / 32, R1, HID_, sW, tid, v);
    #pragma unroll
    for (int q = 0; q < 4; q++) {
        int j = jt + (q << 6);
        #pragma unroll
        for (int rr = 0; rr < 4; rr++) {
            int b = b0 + rg * 4 + rr;
            out[((size_t)b * WIN_ + step) * HID_ + j] = v[q][rr];
        }
    }
}

// ============ SERIAL PHASE: persistent, whole-layer x staging, no inner syncs ============
// grid = 128 CTAs (8 j-slices x 16 row-slices of 32 rows), all resident.
// smem: W slices 29x1024 floats (116 KB) + layer-x 32x416 floats (52 KB).

// stage an entire layer's x (32 rows x K floats) via cp.async.cg, one commit.
__device__ __forceinline__ void s_stage_layer(int layer, int s, int step, int row0,
                                              float* dst, int tid) {
    const int str4 = (layer == 0) ? (K1P_ >> 2) : (HID_ >> 2);   // float4 per row
    const int n4   = SROWS_ * str4;
    for (int i = tid; i < n4; i += 512) {
        int r = i / str4;
        int k = (i - r * str4) << 2;
        uint32_t d = (uint32_t)__cvta_generic_to_shared(dst + r * (str4 << 2) + k);
        const float* src;
        int sz = 16;
        if (layer == 0) {
            if (k < HID_)           src = g_lastall[s] + (size_t)(row0 + r) * HID_ + k;
            else if (k + 4 <= K1_)  src = g_ls + ((size_t)step * B_ + row0 + r) * LOGSIG_ + (k - HID_);
            else                  { src = g_ls; sz = 0; }       // zero-fill pad
        } else if (layer == 1) {
            src = g_h1 + (size_t)(row0 + r) * HID_ + k;
        } else {
            src = g_h2 + (size_t)(row0 + r) * HID_ + k;
        }
        asm volatile("cp.async.cg.shared.global [%0], [%1], 16, %2;"
                     :: "r"(d), "l"(src), "r"(sz));
    }
    asm volatile("cp.async.commit_group;");
    asm volatile("cp.async.wait_group 0;");
    __syncthreads();
}

// one layer GEMM, straight-line over ntile k-tiles, no syncs.
__device__ __forceinline__ void s_layer_ns(int ntile, int tile0, int xstride,
                                           const float* __restrict__ sW,
                                           const float* __restrict__ sX,
                                           int jl, int rg, float outv[2]) {
    unsigned long long acc[2] = {0ULL, 0ULL};
    for (int t = 0; t < ntile; t++) {
        const float* wt = sW + (tile0 + t) * 1024;
        ulonglong2 w2[8];
        #pragma unroll
        for (int c4 = 0; c4 < 8; c4++)
            w2[c4] = *reinterpret_cast<const ulonglong2*>(
                wt + jl * 32 + ((c4 ^ (jl & 7)) << 2));
        #pragma unroll
        for (int r = 0; r < 2; r++) {
            const float* xr = sX + ((rg << 1) + r) * xstride + (t << 5);
            #pragma unroll
            for (int c4 = 0; c4 < 8; c4++) {
                ulonglong2 x2 = *reinterpret_cast<const ulonglong2*>(xr + (c4 << 2));
                ffma2(acc[r], w2[c4].x, x2.x);
                ffma2(acc[r], w2[c4].y, x2.y);
            }
        }
    }
    #pragma unroll
    for (int r = 0; r < 2; r++) {
        float lo = __uint_as_float((unsigned)acc[r]);
        float hi = __uint_as_float((unsigned)(acc[r] >> 32));
        outv[r] = lo + hi;
    }
}

// grid-wide barrier: arrive via one atomic, poll via acquire loads.
__device__ __forceinline__ void gbar(int target) {
    __threadfence();
    __syncthreads();
    if (threadIdx.x == 0) {
        atomicAdd(&g_barcnt, 1);
        int v;
        do {
            asm volatile("ld.global.acquire.gpu.b32 %0, [%1];"
                         : "=r"(v) : "l"(&g_barcnt));
        } while (v < target);
    }
    __syncthreads();
}

__global__ void __launch_bounds__(512, 1)
serial_persist_kernel(const float* __restrict__ W1, const float* __restrict__ b1,
                      const float* __restrict__ W2, const float* __restrict__ b2,
                      const float* __restrict__ W3, const float* __restrict__ b3)
{
    extern __shared__ float smem[];
    float* sW = smem;                       // 29 tiles x 32j x 32k (swizzled)
    float* sX = sW + S_TILES_ * 1024;       // 32 rows x up to 416 floats

    const int tid = threadIdx.x;
    const int jl  = tid & 31;
    const int rg  = tid >> 5;               // 0..15, 2 rows each
    const int jg  = blockIdx.x & 7;
    const int rb  = blockIdx.x >> 3;        // 0..15
    const int j   = (jg << 5) + jl;
    const int row0 = rb * SROWS_;           // 32 rows per CTA

    const float bb1 = b1[j], bb2 = b2[j], bb3 = b3[j];

    // ---- load W slices (once), swizzled ----
    for (int idx = tid; idx < S_TILES_ * 256; idx += 512) {
        int t   = idx >> 8;
        int w   = idx & 255;
        int r   = w >> 3;
        int c4  = w & 7;
        const float* Wg; int K; int kq;
        if (t < 13)      { Wg = W1; K = K1_;  kq = t; }
        else if (t < 21) { Wg = W2; K = HID_; kq = t - 13; }
        else             { Wg = W3; K = HID_; kq = t - 21; }
        int k = (kq << 5) + (c4 << 2);
        float4 v = make_float4(0.f, 0.f, 0.f, 0.f);
        if (k + 4 <= K)
            v = *reinterpret_cast<const float4*>(Wg + (size_t)((jg << 5) + r) * K + k);
        *reinterpret_cast<float4*>(sW + t * 1024 + r * 32 + ((c4 ^ (r & 7)) << 2)) = v;
    }
    __syncthreads();

    const int nupd = g_nupd;                // 21
    int bar = 0;
    for (int si = 0; si < nupd; si++) {
        const int step = g_ustep[si];
        float v[2];

        s_stage_layer(0, si, step, row0, sX, tid);
        s_layer_ns(13, 0, K1P_, sW, sX, jl, rg, v);
        #pragma unroll
        for (int r = 0; r < 2; r++)
            g_h1[(size_t)(row0 + (rg << 1) + r) * HID_ + j] = fmaxf(v[r] + bb1, 0.f);
        bar += SGRID_; gbar(bar);

        s_stage_layer(1, si, step, row0, sX, tid);
        s_layer_ns(8, 13, HID_, sW, sX, jl, rg, v);
        #pragma unroll
        for (int r = 0; r < 2; r++)
            g_h2[(size_t)(row0 + (rg << 1) + r) * HID_ + j] = fmaxf(v[r] + bb2, 0.f);
        bar += SGRID_; gbar(bar);

        s_stage_layer(2, si, step, row0, sX, tid);
        s_layer_ns(8, 21, HID_, sW, sX, jl, rg, v);
        #pragma unroll
        for (int r = 0; r < 2; r++)
            g_lastall[si + 1][(size_t)(row0 + (rg << 1) + r) * HID_ + j] = tanhf(v[r] + bb3);
        if (si + 1 < nupd) { bar += SGRID_; gbar(bar); }
    }
}

extern "C" void kernel_launch(void* const* d_in, const int* in_sizes, int n_in,
                              void* d_out, int out_size) {
    (void)in_sizes; (void)n_in; (void)out_size;
    const float* z  = (const float*)d_in[0];
    const float* W1 = (const float*)d_in[1];
    const float* b1 = (const float*)d_in[2];
    const float* W2 = (const float*)d_in[3];
    const float* b2 = (const float*)d_in[4];
    const float* W3 = (const float*)d_in[5];
    const float* b3 = (const float*)d_in[6];
    const float* Wl = (const float*)d_in[7];
    float* out = (float*)d_out;

    const size_t smem_par =
        (2 * WTS_ + BT_ * K1P_ + BT_ * HID_) * sizeof(float);     // ~108 KB
    const size_t smem_ser =
        (S_TILES_ * 1024 + SXF_) * sizeof(float);                 // ~168 KB
    cudaFuncSetAttribute(rnn_all_kernel,
                         cudaFuncAttributeMaxDynamicSharedMemorySize, (int)smem_par);
    cudaFuncSetAttribute(serial_persist_kernel,
                         cudaFuncAttributeMaxDynamicSharedMemorySize, (int)smem_ser);

    sched_kernel<<<1, 256>>>();
    zero_last_kernel<<<(B_ * HID_ + 255) / 256, 256>>>();
    cumsum_part_kernel<<<(B_ * NCH_ * 4) / 256, 256>>>(z);
    cumsum_write_kernel<<<(B_ * NCH_ * 4) / 256, 256>>>(z);
    logsig_kernel<<<dim3(WIN_, B_), 160>>>();

    serial_persist_kernel<<<SGRID_, 512, smem_ser>>>(W1, b1, W2, b2, W3, b3);

    rnn_all_kernel<<<WIN_ * (B_ / BT_), 256, smem_par>>>(
        W1, b1, W2, b2, W3, b3, Wl, out);
}